// round 8
// baseline (speedup 1.0000x reference)
#include <cuda_runtime.h>
#include <cstdint>

#ifndef NEG_INF_F
#define NEG_INF_F __int_as_float(0xff800000)
#endif

// Exact strict-'>' insertion of (x, j) into the running top-4.
// Ties keep the earlier (smaller) edge index, matching the reference.
__device__ __forceinline__ void ins4(float x, int j,
                                     float& v0, float& v1, float& v2, float& v3,
                                     int& i0, int& i1, int& i2, int& i3)
{
    if (x > v3) {
        if (x > v1) {
            if (x > v0) {
                v3 = v2; i3 = i2;
                v2 = v1; i2 = i1;
                v1 = v0; i1 = i0;
                v0 = x;  i0 = j;
            } else {
                v3 = v2; i3 = i2;
                v2 = v1; i2 = i1;
                v1 = x;  i1 = j;
            }
        } else {
            if (x > v2) {
                v3 = v2; i3 = i2;
                v2 = x;  i2 = j;
            } else {
                v3 = x;  i3 = j;
            }
        }
    }
}

// Quad max written as a chain so ptxas can fuse into FMNMX3 + FMNMX.
__device__ __forceinline__ float qmax(float4 a)
{
    return fmaxf(fmaxf(fmaxf(a.x, a.y), a.z), a.w);
}

__device__ __forceinline__ void ins_quad(float4 a, int j,
                                         float& v0, float& v1, float& v2, float& v3,
                                         int& i0, int& i1, int& i2, int& i3)
{
    ins4(a.x, j + 0, v0, v1, v2, v3, i0, i1, i2, i3);
    ins4(a.y, j + 1, v0, v1, v2, v3, i0, i1, i2, i3);
    ins4(a.z, j + 2, v0, v1, v2, v3, i0, i1, i2, i3);
    ins4(a.w, j + 3, v0, v1, v2, v3, i0, i1, i2, i3);
}

// One thread per node. Unroll-16 body: 4 front-batched LDG.128 (MLP=4),
// per-quad max fast-reject (strict '>' makes reject exact), scalar fixups.
__global__ void __launch_bounds__(256) segment_top4_kernel(
    const int* __restrict__ row_ptr,
    const float* __restrict__ scores,
    float* __restrict__ vals_out,   // [N,4] float32
    float* __restrict__ idxf_out,   // [N,4] float32 (index values; exact < 2^24)
    int n_nodes)
{
    int i = blockIdx.x * blockDim.x + threadIdx.x;
    if (i >= n_nodes) return;

    int s = __ldg(row_ptr + i);
    int e = __ldg(row_ptr + i + 1);

    float v0 = NEG_INF_F, v1 = NEG_INF_F, v2 = NEG_INF_F, v3 = NEG_INF_F;
    int   i0 = -1, i1 = -1, i2 = -1, i3 = -1;

    int j = s;

    // Scalar head to reach 16B alignment.
    int head_end = (s + 3) & ~3;
    if (head_end > e) head_end = e;
    for (; j < head_end; ++j)
        ins4(__ldg(scores + j), j, v0, v1, v2, v3, i0, i1, i2, i3);

    const float4* sv = reinterpret_cast<const float4*>(scores);

    // 16-edge body: 4 independent LDG.128 in flight, 4 quad-maxes, 4 tests.
    for (; j + 16 <= e; j += 16) {
        int q = j >> 2;
        float4 a = __ldg(sv + q);
        float4 b = __ldg(sv + q + 1);
        float4 c = __ldg(sv + q + 2);
        float4 d = __ldg(sv + q + 3);
        float ma = qmax(a), mb = qmax(b), mc = qmax(c), md = qmax(d);
        if (ma > v3) ins_quad(a, j,      v0, v1, v2, v3, i0, i1, i2, i3);
        if (mb > v3) ins_quad(b, j + 4,  v0, v1, v2, v3, i0, i1, i2, i3);
        if (mc > v3) ins_quad(c, j + 8,  v0, v1, v2, v3, i0, i1, i2, i3);
        if (md > v3) ins_quad(d, j + 12, v0, v1, v2, v3, i0, i1, i2, i3);
    }

    // 4-edge tail quads.
    for (; j + 4 <= e; j += 4) {
        float4 a = __ldg(sv + (j >> 2));
        if (qmax(a) > v3) ins_quad(a, j, v0, v1, v2, v3, i0, i1, i2, i3);
    }

    // Scalar tail.
    for (; j < e; ++j)
        ins4(__ldg(scores + j), j, v0, v1, v2, v3, i0, i1, i2, i3);

    // Coalesced 16B vector stores.
    reinterpret_cast<float4*>(vals_out)[i] = make_float4(v0, v1, v2, v3);
    reinterpret_cast<float4*>(idxf_out)[i] =
        make_float4((float)i0, (float)i1, (float)i2, (float)i3);
}

extern "C" void kernel_launch(void* const* d_in, const int* in_sizes, int n_in,
                              void* d_out, int out_size)
{
    // row_ptr is the smaller input (N+1) vs edge_scores (E).
    int a = in_sizes[0], b = (n_in > 1) ? in_sizes[1] : 0;
    int rp_slot = (n_in > 1 && b < a) ? 1 : 0;
    const int*   row_ptr = (const int*)d_in[rp_slot];
    const float* scores  = (const float*)d_in[1 - rp_slot];
    long long n = (long long)in_sizes[rp_slot] - 1;

    // Single-dtype (float32) output: vals [N,4] then idx-as-float [N,4].
    float* vals_out = (float*)d_out;
    float* idxf_out = vals_out + n * 4;

    int threads = 256;
    int blocks = (int)((n + threads - 1) / threads);
    segment_top4_kernel<<<blocks, threads>>>(row_ptr, scores, vals_out, idxf_out, (int)n);
}

// round 9
// speedup vs baseline: 1.2819x; 1.2819x over previous
#include <cuda_runtime.h>
#include <cstdint>

#ifndef NEG_INF_F
#define NEG_INF_F __int_as_float(0xff800000)
#endif

// Branchless strict-'>' insertion of (x, j) into the running top-4.
// Pure select chain: no divergent branches inside. Value-only compares
// keep the incumbent on ties == reference's smallest-index tie-break.
// For a non-improving x all predicates are false -> exact no-op.
__device__ __forceinline__ void ins4(float x, int j,
                                     float& v0, float& v1, float& v2, float& v3,
                                     int& i0, int& i1, int& i2, int& i3)
{
    bool c0 = x > v0;
    bool c1 = x > v1;
    bool c2 = x > v2;
    bool c3 = x > v3;
    v3 = c3 ? (c2 ? v2 : x) : v3;   i3 = c3 ? (c2 ? i2 : j) : i3;
    v2 = c2 ? (c1 ? v1 : x) : v2;   i2 = c2 ? (c1 ? i1 : j) : i2;
    v1 = c1 ? (c0 ? v0 : x) : v1;   i1 = c1 ? (c0 ? i0 : j) : i1;
    v0 = c0 ? x : v0;               i0 = c0 ? j : i0;
}

// One thread per node. 8-edge body (2 x LDG.128 in flight), per-quad max
// fast-reject (exact under strict '>'), branchless insertion on hit.
__global__ void __launch_bounds__(256) segment_top4_kernel(
    const int* __restrict__ row_ptr,
    const float* __restrict__ scores,
    float* __restrict__ vals_out,   // [N,4] float32
    float* __restrict__ idxf_out,   // [N,4] float32 (index values; exact < 2^24)
    int n_nodes)
{
    int i = blockIdx.x * blockDim.x + threadIdx.x;
    if (i >= n_nodes) return;

    int s = __ldg(row_ptr + i);
    int e = __ldg(row_ptr + i + 1);

    float v0 = NEG_INF_F, v1 = NEG_INF_F, v2 = NEG_INF_F, v3 = NEG_INF_F;
    int   i0 = -1, i1 = -1, i2 = -1, i3 = -1;

    int j = s;

    // Scalar head to reach 16B alignment (scores base is 256B aligned).
    int head_end = (s + 3) & ~3;
    if (head_end > e) head_end = e;
    for (; j < head_end; ++j)
        ins4(__ldg(scores + j), j, v0, v1, v2, v3, i0, i1, i2, i3);

    const float4* sv = reinterpret_cast<const float4*>(scores);

    // 8-edge body: two LDG.128 in flight per iteration.
    for (; j + 8 <= e; j += 8) {
        float4 a = __ldg(sv + (j >> 2));
        float4 b = __ldg(sv + (j >> 2) + 1);
        float ma = fmaxf(fmaxf(fmaxf(a.x, a.y), a.z), a.w);
        float mb = fmaxf(fmaxf(fmaxf(b.x, b.y), b.z), b.w);
        if (ma > v3) {
            ins4(a.x, j + 0, v0, v1, v2, v3, i0, i1, i2, i3);
            ins4(a.y, j + 1, v0, v1, v2, v3, i0, i1, i2, i3);
            ins4(a.z, j + 2, v0, v1, v2, v3, i0, i1, i2, i3);
            ins4(a.w, j + 3, v0, v1, v2, v3, i0, i1, i2, i3);
        }
        if (mb > v3) {
            ins4(b.x, j + 4, v0, v1, v2, v3, i0, i1, i2, i3);
            ins4(b.y, j + 5, v0, v1, v2, v3, i0, i1, i2, i3);
            ins4(b.z, j + 6, v0, v1, v2, v3, i0, i1, i2, i3);
            ins4(b.w, j + 7, v0, v1, v2, v3, i0, i1, i2, i3);
        }
    }
    for (; j + 4 <= e; j += 4) {
        float4 a = __ldg(sv + (j >> 2));
        float ma = fmaxf(fmaxf(fmaxf(a.x, a.y), a.z), a.w);
        if (ma > v3) {
            ins4(a.x, j + 0, v0, v1, v2, v3, i0, i1, i2, i3);
            ins4(a.y, j + 1, v0, v1, v2, v3, i0, i1, i2, i3);
            ins4(a.z, j + 2, v0, v1, v2, v3, i0, i1, i2, i3);
            ins4(a.w, j + 3, v0, v1, v2, v3, i0, i1, i2, i3);
        }
    }

    // Scalar tail.
    for (; j < e; ++j)
        ins4(__ldg(scores + j), j, v0, v1, v2, v3, i0, i1, i2, i3);

    // Coalesced 16B vector stores.
    reinterpret_cast<float4*>(vals_out)[i] = make_float4(v0, v1, v2, v3);
    reinterpret_cast<float4*>(idxf_out)[i] =
        make_float4((float)i0, (float)i1, (float)i2, (float)i3);
}

extern "C" void kernel_launch(void* const* d_in, const int* in_sizes, int n_in,
                              void* d_out, int out_size)
{
    // row_ptr is the smaller input (N+1) vs edge_scores (E).
    int a = in_sizes[0], b = (n_in > 1) ? in_sizes[1] : 0;
    int rp_slot = (n_in > 1 && b < a) ? 1 : 0;
    const int*   row_ptr = (const int*)d_in[rp_slot];
    const float* scores  = (const float*)d_in[1 - rp_slot];
    long long n = (long long)in_sizes[rp_slot] - 1;

    // Single-dtype (float32) output: vals [N,4] then idx-as-float [N,4].
    float* vals_out = (float*)d_out;
    float* idxf_out = vals_out + n * 4;

    int threads = 256;
    int blocks = (int)((n + threads - 1) / threads);
    segment_top4_kernel<<<blocks, threads>>>(row_ptr, scores, vals_out, idxf_out, (int)n);
}